// round 1
// baseline (speedup 1.0000x reference)
#include <cuda_runtime.h>
#include <cstdint>

#define CDIM 128
#define RNUM 7
#define TNUM 4
#define MAXN 100000
#define KREL (RNUM * CDIM)          /* 896  */
#define KTOT (KREL + TNUM * CDIM)   /* 1408 */

// Scratch (device globals — no runtime allocation allowed)
__device__ float g_sums[(size_t)MAXN * KREL];   // 358.4 MB: per-(node, edge_type) feature sums
__device__ int   g_cnt[MAXN * RNUM];            // per-(node, edge_type) edge counts
__device__ float g_inv[MAXN * RNUM];            // 1 / max(cnt, 1)
__device__ float g_Bt[KTOT * CDIM];             // B matrix, [k][o] row-major (o contiguous)

// ---------------------------------------------------------------------------
// Zero the segment sums + counts
// ---------------------------------------------------------------------------
__global__ void k_init(int nseg) {
    size_t total4 = (size_t)nseg * (CDIM / 4);
    float4 z = make_float4(0.f, 0.f, 0.f, 0.f);
    float4* s4 = reinterpret_cast<float4*>(g_sums);
    size_t stride = (size_t)gridDim.x * blockDim.x;
    for (size_t i = (size_t)blockIdx.x * blockDim.x + threadIdx.x; i < total4; i += stride)
        s4[i] = z;
    for (size_t i = (size_t)blockIdx.x * blockDim.x + threadIdx.x; i < (size_t)nseg; i += stride)
        g_cnt[i] = 0;
}

// ---------------------------------------------------------------------------
// Build Bt[k][o]: k < 896 -> rel_w[r][o][c] (k = r*128+c);
//                 k >= 896 -> root_w[t][o][c] (k-896 = t*128+c)
// ---------------------------------------------------------------------------
__global__ void k_buildB(const float* __restrict__ rel_w,
                         const float* __restrict__ root_w) {
    int idx = blockIdx.x * blockDim.x + threadIdx.x;
    if (idx >= KTOT * CDIM) return;
    int o = idx & (CDIM - 1);
    int k = idx >> 7;
    float v;
    if (k < KREL) {
        int r = k >> 7, c = k & 127;
        v = rel_w[((size_t)(r * CDIM + o)) * CDIM + c];
    } else {
        int t = (k - KREL) >> 7, c = k & 127;
        v = root_w[((size_t)(t * CDIM + o)) * CDIM + c];
    }
    g_Bt[idx] = v;
}

// ---------------------------------------------------------------------------
// Edge pass: one warp per edge. Each lane handles 4 channels (float4).
// Vectorized global reduction (sm_90+): red.global.add.v4.f32
// ---------------------------------------------------------------------------
__global__ void k_edge(const float* __restrict__ x,
                       const int* __restrict__ ei,
                       const int* __restrict__ et, int E) {
    int gtid = blockIdx.x * blockDim.x + threadIdx.x;
    int e = gtid >> 5;
    int lane = gtid & 31;
    if (e >= E) return;
    int src = ei[e];
    int dst = ei[E + e];
    int r = et[e];
    float4 v = reinterpret_cast<const float4*>(x + (size_t)src * CDIM)[lane];
    float* base = g_sums + ((size_t)dst * RNUM + r) * CDIM + lane * 4;
    asm volatile("red.global.add.v4.f32 [%0], {%1,%2,%3,%4};"
                 :: "l"(base), "f"(v.x), "f"(v.y), "f"(v.z), "f"(v.w)
                 : "memory");
    if (lane == 0) atomicAdd(&g_cnt[dst * RNUM + r], 1);
}

// ---------------------------------------------------------------------------
// Reciprocal counts
// ---------------------------------------------------------------------------
__global__ void k_inv(int nseg) {
    int i = blockIdx.x * blockDim.x + threadIdx.x;
    if (i < nseg) g_inv[i] = 1.0f / fmaxf((float)g_cnt[i], 1.0f);
}

// ---------------------------------------------------------------------------
// Fused GEMM: out[n][o] = sum_k A[n][k] * Bt[k][o] + root_b[tnt[n]][o]
//   A[n][k<896]   = sums[n][k] * inv[n][k/128]          (the means)
//   A[n][k>=896]  = (tnt[n] == (k-896)/128) ? x[n][k%128] : 0
// Tile: 128x128, BK=16, 256 threads, 8x8 register microtile.
// ---------------------------------------------------------------------------
__global__ __launch_bounds__(256) void k_gemm(const float* __restrict__ x,
                                              const int* __restrict__ tnt,
                                              const float* __restrict__ root_b,
                                              float* __restrict__ out, int Nn) {
    __shared__ float As[16][128];
    __shared__ float Bs[16][128];
    const int tid = threadIdx.x;
    const int tr = tid >> 4;    // 0..15 -> row group
    const int tc = tid & 15;    // 0..15 -> col group
    const int row0 = blockIdx.x * 128;

    float acc[8][8];
#pragma unroll
    for (int i = 0; i < 8; i++)
#pragma unroll
        for (int j = 0; j < 8; j++) acc[i][j] = 0.f;

    for (int k0 = 0; k0 < KTOT; k0 += 16) {
        // ---- load A tile (128 rows x 16 k), 512 float4 across 256 threads ----
#pragma unroll
        for (int it = 0; it < 2; it++) {
            int idx4 = tid + it * 256;
            int m = idx4 >> 2;            // row within tile
            int kk = (idx4 & 3) * 4;      // k offset within tile (0,4,8,12)
            int n = row0 + m;
            int k = k0 + kk;
            float4 v = make_float4(0.f, 0.f, 0.f, 0.f);
            if (n < Nn) {
                if (k < KREL) {
                    v = *reinterpret_cast<const float4*>(g_sums + (size_t)n * KREL + k);
                    float s = g_inv[n * RNUM + (k >> 7)];
                    v.x *= s; v.y *= s; v.z *= s; v.w *= s;
                } else {
                    int t = (k - KREL) >> 7;
                    if (tnt[n] == t)
                        v = *reinterpret_cast<const float4*>(x + (size_t)n * CDIM + (k & 127));
                }
            }
            As[kk + 0][m] = v.x;
            As[kk + 1][m] = v.y;
            As[kk + 2][m] = v.z;
            As[kk + 3][m] = v.w;
        }
        // ---- load B tile (16 k x 128 o), coalesced float4 ----
#pragma unroll
        for (int it = 0; it < 2; it++) {
            int idx4 = tid + it * 256;
            int kk = idx4 >> 5;           // 0..15
            int o4 = (idx4 & 31) * 4;     // 0..124
            float4 v = *reinterpret_cast<const float4*>(g_Bt + (size_t)(k0 + kk) * CDIM + o4);
            *reinterpret_cast<float4*>(&Bs[kk][o4]) = v;
        }
        __syncthreads();

#pragma unroll
        for (int kk = 0; kk < 16; kk++) {
            float a[8], b[8];
            *reinterpret_cast<float4*>(&a[0]) = *reinterpret_cast<float4*>(&As[kk][tr * 8]);
            *reinterpret_cast<float4*>(&a[4]) = *reinterpret_cast<float4*>(&As[kk][tr * 8 + 4]);
            *reinterpret_cast<float4*>(&b[0]) = *reinterpret_cast<float4*>(&Bs[kk][tc * 8]);
            *reinterpret_cast<float4*>(&b[4]) = *reinterpret_cast<float4*>(&Bs[kk][tc * 8 + 4]);
#pragma unroll
            for (int i = 0; i < 8; i++)
#pragma unroll
                for (int j = 0; j < 8; j++)
                    acc[i][j] += a[i] * b[j];
        }
        __syncthreads();
    }

    // ---- epilogue: add per-type bias, store ----
#pragma unroll
    for (int i = 0; i < 8; i++) {
        int n = row0 + tr * 8 + i;
        if (n >= Nn) continue;
        int t = tnt[n];
#pragma unroll
        for (int j4 = 0; j4 < 2; j4++) {
            int o = tc * 8 + j4 * 4;
            float4 bb = *reinterpret_cast<const float4*>(root_b + t * CDIM + o);
            float4 rv;
            rv.x = acc[i][j4 * 4 + 0] + bb.x;
            rv.y = acc[i][j4 * 4 + 1] + bb.y;
            rv.z = acc[i][j4 * 4 + 2] + bb.z;
            rv.w = acc[i][j4 * 4 + 3] + bb.w;
            *reinterpret_cast<float4*>(out + (size_t)n * CDIM + o) = rv;
        }
    }
}

// ---------------------------------------------------------------------------
extern "C" void kernel_launch(void* const* d_in, const int* in_sizes, int n_in,
                              void* d_out, int out_size) {
    const float* x      = (const float*)d_in[0];
    const int*   ei     = (const int*)d_in[1];
    const int*   et     = (const int*)d_in[2];
    const int*   tnt    = (const int*)d_in[3];
    const float* rel_w  = (const float*)d_in[4];
    const float* root_w = (const float*)d_in[5];
    const float* root_b = (const float*)d_in[6];
    float* out = (float*)d_out;

    int E  = in_sizes[2];   // edge_type element count
    int Nn = in_sizes[3];   // target_node_type element count
    int nseg = Nn * RNUM;

    k_init<<<2048, 256>>>(nseg);
    k_buildB<<<(KTOT * CDIM + 255) / 256, 256>>>(rel_w, root_w);
    k_edge<<<(E * 32 + 255) / 256, 256>>>(x, ei, et, E);
    k_inv<<<(nseg + 255) / 256, 256>>>(nseg);
    k_gemm<<<(Nn + 127) / 128, 256>>>(x, tnt, root_b, out, Nn);
}

// round 3
// speedup vs baseline: 1.4987x; 1.4987x over previous
#include <cuda_runtime.h>
#include <cuda_bf16.h>
#include <cstdint>

#define CDIM 128
#define RNUM 7
#define TNUM 4
#define MAXN 100000
#define KREL (RNUM * CDIM)          /* 896  */
#define KTOT (KREL + TNUM * CDIM)   /* 1408 */
#define KC   64                     /* K per chunk */
#define NCHUNK (KTOT / KC)          /* 22 */
#define BROW_BYTES 128              /* 64 bf16 per row in gmem B */
#define BTILE_BYTES (CDIM * BROW_BYTES)  /* 16 KB per chunk per term */
#define SROW 144                    /* padded smem row stride (bytes) */

// ---------------- device scratch (no runtime allocation allowed) ----------
__device__ float g_sums[(size_t)MAXN * KREL];
__device__ int   g_cnt[MAXN * RNUM];
__device__ float g_inv[MAXN * RNUM];
__device__ __align__(16) char g_Bh[NCHUNK * BTILE_BYTES];  // bf16 hi, [chunk][o][kk]
__device__ __align__(16) char g_Bl[NCHUNK * BTILE_BYTES];  // bf16 lo

// ---------------- helpers ---------------------------------------------------
__device__ __forceinline__ uint32_t smem_u32(const void* p) {
    uint32_t a;
    asm("{ .reg .u64 t; cvta.to.shared.u64 t, %1; cvt.u32.u64 %0, t; }" : "=r"(a) : "l"(p));
    return a;
}
__device__ __forceinline__ void ldmat_x4(uint32_t addr, uint32_t* r) {
    asm volatile("ldmatrix.sync.aligned.m8n8.x4.shared.b16 {%0,%1,%2,%3}, [%4];"
                 : "=r"(r[0]), "=r"(r[1]), "=r"(r[2]), "=r"(r[3]) : "r"(addr));
}
__device__ __forceinline__ void mma_bf16(float* d, const uint32_t* a, const uint32_t* b) {
    asm volatile("mma.sync.aligned.m16n8k16.row.col.f32.bf16.bf16.f32 "
                 "{%0,%1,%2,%3}, {%4,%5,%6,%7}, {%8,%9}, {%0,%1,%2,%3};"
                 : "+f"(d[0]), "+f"(d[1]), "+f"(d[2]), "+f"(d[3])
                 : "r"(a[0]), "r"(a[1]), "r"(a[2]), "r"(a[3]), "r"(b[0]), "r"(b[1]));
}

// ---------------- phase 0: zero segment sums + counts ----------------------
__global__ void k_init(int nseg) {
    size_t total4 = (size_t)nseg * (CDIM / 4);
    float4 z = make_float4(0.f, 0.f, 0.f, 0.f);
    float4* s4 = reinterpret_cast<float4*>(g_sums);
    size_t stride = (size_t)gridDim.x * blockDim.x;
    for (size_t i = (size_t)blockIdx.x * blockDim.x + threadIdx.x; i < total4; i += stride)
        s4[i] = z;
    for (size_t i = (size_t)blockIdx.x * blockDim.x + threadIdx.x; i < (size_t)nseg; i += stride)
        g_cnt[i] = 0;
}

// ---------------- phase 1: build bf16 hi/lo B tiles -------------------------
// B[k][o]: k<896 -> rel_w[r][o][c] (k=r*128+c); else root_w[t][o][c].
// Stored as [chunk][o][kk] (kk contiguous, 64 per chunk) = natural ldmatrix layout.
__global__ void k_buildB(const float* __restrict__ rel_w,
                         const float* __restrict__ root_w) {
    int idx = blockIdx.x * blockDim.x + threadIdx.x;
    if (idx >= KTOT * CDIM) return;
    int k = idx >> 7;               // 0..1407
    int o = idx & 127;
    float v;
    if (k < KREL) {
        int r = k >> 7, c = k & 127;
        v = rel_w[((size_t)(r * CDIM + o)) * CDIM + c];
    } else {
        int t = (k - KREL) >> 7, c = k & 127;
        v = root_w[((size_t)(t * CDIM + o)) * CDIM + c];
    }
    __nv_bfloat16 hi = __float2bfloat16(v);
    __nv_bfloat16 lo = __float2bfloat16(v - __bfloat162float(hi));
    int chunk = k >> 6, kk = k & 63;
    size_t off = (size_t)chunk * BTILE_BYTES + (size_t)o * BROW_BYTES + kk * 2;
    *reinterpret_cast<__nv_bfloat16*>(g_Bh + off) = hi;
    *reinterpret_cast<__nv_bfloat16*>(g_Bl + off) = lo;
}

// ---------------- phase 2: edge scatter (one warp per edge) ----------------
__global__ void k_edge(const float* __restrict__ x,
                       const int* __restrict__ ei,
                       const int* __restrict__ et, int E) {
    int gtid = blockIdx.x * blockDim.x + threadIdx.x;
    int e = gtid >> 5;
    int lane = gtid & 31;
    if (e >= E) return;
    int src = ei[e];
    int dst = ei[E + e];
    int r = et[e];
    float4 v = reinterpret_cast<const float4*>(x + (size_t)src * CDIM)[lane];
    float* base = g_sums + ((size_t)dst * RNUM + r) * CDIM + lane * 4;
    asm volatile("red.global.add.v4.f32 [%0], {%1,%2,%3,%4};"
                 :: "l"(base), "f"(v.x), "f"(v.y), "f"(v.z), "f"(v.w) : "memory");
    if (lane == 0) atomicAdd(&g_cnt[dst * RNUM + r], 1);
}

__global__ void k_inv(int nseg) {
    int i = blockIdx.x * blockDim.x + threadIdx.x;
    if (i < nseg) g_inv[i] = 1.0f / fmaxf((float)g_cnt[i], 1.0f);
}

// ---------------- phase 3: HMMA bf16 hi/lo GEMM ------------------------------
// out[128-tile][128] = A[128][1408] @ B^T (+bias). SMEM single-buffered KC=64 chunks.
#define SM_AHI 0
#define SM_ALO (SM_AHI + 128 * SROW)
#define SM_BHI (SM_ALO + 128 * SROW)
#define SM_BLO (SM_BHI + 128 * SROW)
#define SM_TOTAL (SM_BLO + 128 * SROW)   /* 73728 B */

__global__ __launch_bounds__(256, 1) void k_gemm_mma(const float* __restrict__ x,
                                                     const int* __restrict__ tnt,
                                                     const float* __restrict__ root_b,
                                                     float* __restrict__ out, int Nn) {
    extern __shared__ char smem[];
    const uint32_t sb = smem_u32(smem);
    const int tid = threadIdx.x;
    const int wid = tid >> 5;
    const int lane = tid & 31;
    const int row0 = blockIdx.x * 128;

    // A-build assignment
    const int m = tid >> 1;
    const int khalf = (tid & 1) * 32;
    const int n = row0 + m;
    const bool nval = (n < Nn);
    const int mytype = nval ? tnt[n] : -1;

    // warp tiling: 4 (M) x 2 (N); warp tile 32 x 64
    const int wm0 = (wid & 3) * 32;
    const int wn0 = (wid >> 2) * 64;

    // ldmatrix lane-address components
    const int quad = lane >> 3;
    const int lrow = lane & 7;
    // A x4: row = base + (quad&1)*8 + lrow ; kcol = (quad>>1)*8
    const int a_roff = ((quad & 1) * 8 + lrow) * SROW + ((quad >> 1) * 8) * 2;
    // B x4: row = base + (quad>>1)*8 + lrow ; kcol = (quad&1)*8
    const int b_roff = ((quad >> 1) * 8 + lrow) * SROW + ((quad & 1) * 8) * 2;

    float acc[2][8][4];
#pragma unroll
    for (int i = 0; i < 2; i++)
#pragma unroll
        for (int j = 0; j < 8; j++)
#pragma unroll
            for (int q = 0; q < 4; q++) acc[i][j][q] = 0.f;

    for (int c = 0; c < NCHUNK; ++c) {
        __syncthreads();   // protect smem from previous iteration's readers

        // ---- build A hi/lo tile: 32 fp32 per thread ----
        float4 v[8];
        if (c < 14) {
            const int r = c >> 1;
            if (nval) {
                const float s = g_inv[n * RNUM + r];
                const float4* src = reinterpret_cast<const float4*>(
                    g_sums + (size_t)n * KREL + c * KC + khalf);
#pragma unroll
                for (int i = 0; i < 8; i++) {
                    v[i] = src[i];
                    v[i].x *= s; v[i].y *= s; v[i].z *= s; v[i].w *= s;
                }
            } else {
#pragma unroll
                for (int i = 0; i < 8; i++) v[i] = make_float4(0.f, 0.f, 0.f, 0.f);
            }
        } else {
            const int t = (c - 14) >> 1;
            const int coloff = (c & 1) * 64 + khalf;
            if (nval && mytype == t) {
                const float4* src = reinterpret_cast<const float4*>(
                    x + (size_t)n * CDIM + coloff);
#pragma unroll
                for (int i = 0; i < 8; i++) v[i] = src[i];
            } else {
#pragma unroll
                for (int i = 0; i < 8; i++) v[i] = make_float4(0.f, 0.f, 0.f, 0.f);
            }
        }
        {
            const uint32_t hiB = sb + SM_AHI + m * SROW;
            const uint32_t loB = sb + SM_ALO + m * SROW;
#pragma unroll
            for (int g = 0; g < 4; g++) {
                const float f[8] = {
                    v[2 * g].x, v[2 * g].y, v[2 * g].z, v[2 * g].w,
                    v[2 * g + 1].x, v[2 * g + 1].y, v[2 * g + 1].z, v[2 * g + 1].w };
                uint32_t hp[4], lp[4];
#pragma unroll
                for (int j = 0; j < 4; j++) {
                    __nv_bfloat16 h0 = __float2bfloat16(f[2 * j]);
                    __nv_bfloat16 h1 = __float2bfloat16(f[2 * j + 1]);
                    __nv_bfloat16 l0 = __float2bfloat16(f[2 * j]     - __bfloat162float(h0));
                    __nv_bfloat16 l1 = __float2bfloat16(f[2 * j + 1] - __bfloat162float(h1));
                    hp[j] = (uint32_t)__bfloat16_as_ushort(h0) |
                            ((uint32_t)__bfloat16_as_ushort(h1) << 16);
                    lp[j] = (uint32_t)__bfloat16_as_ushort(l0) |
                            ((uint32_t)__bfloat16_as_ushort(l1) << 16);
                }
                const uint32_t off = (khalf + g * 8) * 2;
                asm volatile("st.shared.v4.b32 [%0], {%1,%2,%3,%4};"
                             :: "r"(hiB + off), "r"(hp[0]), "r"(hp[1]), "r"(hp[2]), "r"(hp[3]) : "memory");
                asm volatile("st.shared.v4.b32 [%0], {%1,%2,%3,%4};"
                             :: "r"(loB + off), "r"(lp[0]), "r"(lp[1]), "r"(lp[2]), "r"(lp[3]) : "memory");
            }
        }
        // ---- copy B hi/lo (16 KB each) to padded smem rows ----
        {
            const char* srcH = g_Bh + (size_t)c * BTILE_BYTES;
            const char* srcL = g_Bl + (size_t)c * BTILE_BYTES;
#pragma unroll
            for (int i = 0; i < 4; i++) {
                int u = tid + i * 256;          // 0..1023
                int row = u >> 3, seg = (u & 7) * 16;
                float4 vh = *reinterpret_cast<const float4*>(srcH + row * BROW_BYTES + seg);
                float4 vl = *reinterpret_cast<const float4*>(srcL + row * BROW_BYTES + seg);
                *reinterpret_cast<float4*>(smem + SM_BHI + row * SROW + seg) = vh;
                *reinterpret_cast<float4*>(smem + SM_BLO + row * SROW + seg) = vl;
            }
        }
        __syncthreads();

        // ---- 4 k16 steps of HMMA ----
#pragma unroll
        for (int s = 0; s < 4; s++) {
            uint32_t ah[2][4], al[2][4];     // [m-subtile][4]
            uint32_t bh[4][4], bl[4][4];     // [n-pair][4] (2 n-tiles per x4)
#pragma unroll
            for (int ms = 0; ms < 2; ms++) {
                uint32_t base = (wm0 + ms * 16) * SROW + (s * 16) * 2 + a_roff;
                ldmat_x4(sb + SM_AHI + base, ah[ms]);
                ldmat_x4(sb + SM_ALO + base, al[ms]);
            }
#pragma unroll
            for (int jp = 0; jp < 4; jp++) {
                uint32_t base = (wn0 + jp * 16) * SROW + (s * 16) * 2 + b_roff;
                ldmat_x4(sb + SM_BHI + base, bh[jp]);
                ldmat_x4(sb + SM_BLO + base, bl[jp]);
            }
#pragma unroll
            for (int ms = 0; ms < 2; ms++)
#pragma unroll
                for (int jp = 0; jp < 4; jp++) {
                    mma_bf16(acc[ms][2 * jp],     ah[ms], &bh[jp][0]);
                    mma_bf16(acc[ms][2 * jp + 1], ah[ms], &bh[jp][2]);
                    mma_bf16(acc[ms][2 * jp],     ah[ms], &bl[jp][0]);
                    mma_bf16(acc[ms][2 * jp + 1], ah[ms], &bl[jp][2]);
                    mma_bf16(acc[ms][2 * jp],     al[ms], &bh[jp][0]);
                    mma_bf16(acc[ms][2 * jp + 1], al[ms], &bh[jp][2]);
                }
        }
    }

    // ---- epilogue: add per-row bias, store ----
    const int g = lane >> 2;
    const int tig = lane & 3;
#pragma unroll
    for (int ms = 0; ms < 2; ms++) {
        const int r1 = row0 + wm0 + ms * 16 + g;
        const int r2 = r1 + 8;
        const bool ok1 = (r1 < Nn), ok2 = (r2 < Nn);
        const int t1 = ok1 ? tnt[r1] : 0;
        const int t2 = ok2 ? tnt[r2] : 0;
#pragma unroll
        for (int nt = 0; nt < 8; nt++) {
            const int col = wn0 + nt * 8 + tig * 2;
            if (ok1) {
                float2 b1 = *reinterpret_cast<const float2*>(root_b + t1 * CDIM + col);
                float2 o1;
                o1.x = acc[ms][nt][0] + b1.x;
                o1.y = acc[ms][nt][1] + b1.y;
                *reinterpret_cast<float2*>(out + (size_t)r1 * CDIM + col) = o1;
            }
            if (ok2) {
                float2 b2 = *reinterpret_cast<const float2*>(root_b + t2 * CDIM + col);
                float2 o2;
                o2.x = acc[ms][nt][2] + b2.x;
                o2.y = acc[ms][nt][3] + b2.y;
                *reinterpret_cast<float2*>(out + (size_t)r2 * CDIM + col) = o2;
            }
        }
    }
}

// ---------------------------------------------------------------------------
extern "C" void kernel_launch(void* const* d_in, const int* in_sizes, int n_in,
                              void* d_out, int out_size) {
    const float* x      = (const float*)d_in[0];
    const int*   ei     = (const int*)d_in[1];
    const int*   et     = (const int*)d_in[2];
    const int*   tnt    = (const int*)d_in[3];
    const float* rel_w  = (const float*)d_in[4];
    const float* root_w = (const float*)d_in[5];
    const float* root_b = (const float*)d_in[6];
    float* out = (float*)d_out;

    int E  = in_sizes[2];
    int Nn = in_sizes[3];
    int nseg = Nn * RNUM;

    cudaFuncSetAttribute(k_gemm_mma, cudaFuncAttributeMaxDynamicSharedMemorySize, SM_TOTAL);

    k_init<<<2048, 256>>>(nseg);
    k_buildB<<<(KTOT * CDIM + 255) / 256, 256>>>(rel_w, root_w);
    k_edge<<<(E * 32 + 255) / 256, 256>>>(x, ei, et, E);
    k_inv<<<(nseg + 255) / 256, 256>>>(nseg);
    k_gemm_mma<<<(Nn + 127) / 128, 256, SM_TOTAL>>>(x, tnt, root_b, out, Nn);
}

// round 4
// speedup vs baseline: 1.6036x; 1.0700x over previous
#include <cuda_runtime.h>
#include <cuda_bf16.h>
#include <cstdint>

#define CDIM 128
#define RNUM 7
#define TNUM 4
#define MAXN 100000
#define NREL (RNUM * CDIM)          /* 896: transform GEMM N */
#define KROOT (TNUM * CDIM)         /* 512: root GEMM K */
#define BROW_BYTES 128              /* 64 bf16 per row per chunk */
#define BTILE_BYTES (CDIM * BROW_BYTES)  /* 16 KB */
#define SROW 144                    /* padded smem row stride (bytes) */

// ---------------- device scratch ----------------
__device__ float g_y[(size_t)MAXN * NREL];                    // 358 MB transformed feats
__device__ int   g_cnt[MAXN * RNUM];
__device__ float g_inv[MAXN * RNUM];
__device__ __align__(16) char g_TBh[14 * BTILE_BYTES];        // rel_w bf16 hi  [chunk][o][kk]
__device__ __align__(16) char g_TBl[14 * BTILE_BYTES];        // rel_w bf16 lo
__device__ __align__(16) char g_RBh[8 * BTILE_BYTES];         // root_w bf16 hi
__device__ __align__(16) char g_RBl[8 * BTILE_BYTES];         // root_w bf16 lo

// ---------------- helpers ----------------
__device__ __forceinline__ uint32_t smem_u32(const void* p) {
    uint32_t a;
    asm("{ .reg .u64 t; cvta.to.shared.u64 t, %1; cvt.u32.u64 %0, t; }" : "=r"(a) : "l"(p));
    return a;
}
__device__ __forceinline__ void ldmat_x4(uint32_t addr, uint32_t* r) {
    asm volatile("ldmatrix.sync.aligned.m8n8.x4.shared.b16 {%0,%1,%2,%3}, [%4];"
                 : "=r"(r[0]), "=r"(r[1]), "=r"(r[2]), "=r"(r[3]) : "r"(addr));
}
__device__ __forceinline__ void mma_bf16(float* d, const uint32_t* a, const uint32_t* b) {
    asm volatile("mma.sync.aligned.m16n8k16.row.col.f32.bf16.bf16.f32 "
                 "{%0,%1,%2,%3}, {%4,%5,%6,%7}, {%8,%9}, {%0,%1,%2,%3};"
                 : "+f"(d[0]), "+f"(d[1]), "+f"(d[2]), "+f"(d[3])
                 : "r"(a[0]), "r"(a[1]), "r"(a[2]), "r"(a[3]), "r"(b[0]), "r"(b[1]));
}
// split 32 fp32 (8 x float4) into hi/lo bf16 rows in smem (padded SROW layout)
__device__ __forceinline__ void store_hilo(uint32_t hiB, uint32_t loB, int khalf,
                                           const float4* v) {
#pragma unroll
    for (int g = 0; g < 4; g++) {
        const float f[8] = { v[2*g].x, v[2*g].y, v[2*g].z, v[2*g].w,
                             v[2*g+1].x, v[2*g+1].y, v[2*g+1].z, v[2*g+1].w };
        uint32_t hp[4], lp[4];
#pragma unroll
        for (int j = 0; j < 4; j++) {
            __nv_bfloat16 h0 = __float2bfloat16(f[2*j]);
            __nv_bfloat16 h1 = __float2bfloat16(f[2*j+1]);
            __nv_bfloat16 l0 = __float2bfloat16(f[2*j]   - __bfloat162float(h0));
            __nv_bfloat16 l1 = __float2bfloat16(f[2*j+1] - __bfloat162float(h1));
            hp[j] = (uint32_t)__bfloat16_as_ushort(h0) | ((uint32_t)__bfloat16_as_ushort(h1) << 16);
            lp[j] = (uint32_t)__bfloat16_as_ushort(l0) | ((uint32_t)__bfloat16_as_ushort(l1) << 16);
        }
        const uint32_t off = (khalf + g * 8) * 2;
        asm volatile("st.shared.v4.b32 [%0], {%1,%2,%3,%4};"
                     :: "r"(hiB + off), "r"(hp[0]), "r"(hp[1]), "r"(hp[2]), "r"(hp[3]) : "memory");
        asm volatile("st.shared.v4.b32 [%0], {%1,%2,%3,%4};"
                     :: "r"(loB + off), "r"(lp[0]), "r"(lp[1]), "r"(lp[2]), "r"(lp[3]) : "memory");
    }
}

// ---------------- phase 0: zero counts ----------------
__global__ void k_zero(int nseg) {
    int i = blockIdx.x * blockDim.x + threadIdx.x;
    if (i < nseg) g_cnt[i] = 0;
}

// ---------------- phase 1: counts + inv ----------------
__global__ void k_count(const int* __restrict__ ei, const int* __restrict__ et, int E) {
    int e = blockIdx.x * blockDim.x + threadIdx.x;
    if (e >= E) return;
    atomicAdd(&g_cnt[ei[E + e] * RNUM + et[e]], 1);
}
__global__ void k_inv(int nseg) {
    int i = blockIdx.x * blockDim.x + threadIdx.x;
    if (i < nseg) g_inv[i] = 1.0f / fmaxf((float)g_cnt[i], 1.0f);
}

// ---------------- phase 2: build bf16 hi/lo weight tiles ----------------
// k<896: rel_w[r][o][c] -> g_TB[(r*2+(c>>6))][o][c&63]
// else : root_w[t][o][c] -> g_RB[(t*2+(c>>6))][o][c&63]
__global__ void k_buildB(const float* __restrict__ rel_w,
                         const float* __restrict__ root_w) {
    int idx = blockIdx.x * blockDim.x + threadIdx.x;
    if (idx >= (NREL + KROOT) * CDIM) return;
    int k = idx >> 7;
    int o = idx & 127;
    float v; char *dh, *dl; int chunk;
    int c = k & 127;
    if (k < NREL) {
        int r = k >> 7;
        v = rel_w[((size_t)(r * CDIM + o)) * CDIM + c];
        chunk = r * 2 + (c >> 6); dh = g_TBh; dl = g_TBl;
    } else {
        int t = (k - NREL) >> 7;
        v = root_w[((size_t)(t * CDIM + o)) * CDIM + c];
        chunk = t * 2 + (c >> 6); dh = g_RBh; dl = g_RBl;
    }
    __nv_bfloat16 hi = __float2bfloat16(v);
    __nv_bfloat16 lo = __float2bfloat16(v - __bfloat162float(hi));
    size_t off = (size_t)chunk * BTILE_BYTES + (size_t)o * BROW_BYTES + (c & 63) * 2;
    *reinterpret_cast<__nv_bfloat16*>(dh + off) = hi;
    *reinterpret_cast<__nv_bfloat16*>(dl + off) = lo;
}

// ---------------- shared GEMM smem layout ----------------
#define SM_AHI 0
#define SM_ALO (SM_AHI + 128 * SROW)
#define SM_BHI (SM_ALO + 128 * SROW)
#define SM_BLO (SM_BHI + 128 * SROW)
#define SM_TOTAL (SM_BLO + 128 * SROW)   /* 73728 B */

// ---------------- phase 3: transform GEMM  y[n][r*128+o] = x @ rel_w^T -----
// grid (7, mtiles): blockIdx.x = r (n-tile), blockIdx.y = m-tile. K=128 (2 chunks).
__global__ __launch_bounds__(256) void k_transform(const float* __restrict__ x,
                                                   float* __restrict__ y, int Nn) {
    extern __shared__ char smem[];
    const uint32_t sb = smem_u32(smem);
    const int tid = threadIdx.x, wid = tid >> 5, lane = tid & 31;
    const int r = blockIdx.x;
    const int row0 = blockIdx.y * 128;

    const int m = tid >> 1;
    const int khalf = (tid & 1) * 32;
    const int n = row0 + m;
    const bool nval = (n < Nn);

    const int wm0 = (wid & 3) * 32;
    const int wn0 = (wid >> 2) * 64;
    const int quad = lane >> 3, lrow = lane & 7;
    const int a_roff = ((quad & 1) * 8 + lrow) * SROW + ((quad >> 1) * 8) * 2;
    const int b_roff = ((quad >> 1) * 8 + lrow) * SROW + ((quad & 1) * 8) * 2;

    float acc[2][8][4];
#pragma unroll
    for (int i = 0; i < 2; i++)
#pragma unroll
        for (int j = 0; j < 8; j++)
#pragma unroll
            for (int q = 0; q < 4; q++) acc[i][j][q] = 0.f;

    for (int c = 0; c < 2; ++c) {
        if (c) __syncthreads();
        // A tile: x rows, fp32 -> hi/lo
        float4 v[8];
        if (nval) {
            const float4* src = reinterpret_cast<const float4*>(x + (size_t)n * CDIM + c * 64 + khalf);
#pragma unroll
            for (int i = 0; i < 8; i++) v[i] = src[i];
        } else {
#pragma unroll
            for (int i = 0; i < 8; i++) v[i] = make_float4(0.f, 0.f, 0.f, 0.f);
        }
        store_hilo(sb + SM_AHI + m * SROW, sb + SM_ALO + m * SROW, khalf, v);
        // B tile copy (pre-split)
        {
            const char* srcH = g_TBh + (size_t)(r * 2 + c) * BTILE_BYTES;
            const char* srcL = g_TBl + (size_t)(r * 2 + c) * BTILE_BYTES;
#pragma unroll
            for (int i = 0; i < 4; i++) {
                int u = tid + i * 256;
                int row = u >> 3, seg = (u & 7) * 16;
                *reinterpret_cast<float4*>(smem + SM_BHI + row * SROW + seg) =
                    *reinterpret_cast<const float4*>(srcH + row * BROW_BYTES + seg);
                *reinterpret_cast<float4*>(smem + SM_BLO + row * SROW + seg) =
                    *reinterpret_cast<const float4*>(srcL + row * BROW_BYTES + seg);
            }
        }
        __syncthreads();
#pragma unroll
        for (int s = 0; s < 4; s++) {
            uint32_t ah[2][4], al[2][4], bh[4][4], bl[4][4];
#pragma unroll
            for (int ms = 0; ms < 2; ms++) {
                uint32_t base = (wm0 + ms * 16) * SROW + (s * 16) * 2 + a_roff;
                ldmat_x4(sb + SM_AHI + base, ah[ms]);
                ldmat_x4(sb + SM_ALO + base, al[ms]);
            }
#pragma unroll
            for (int jp = 0; jp < 4; jp++) {
                uint32_t base = (wn0 + jp * 16) * SROW + (s * 16) * 2 + b_roff;
                ldmat_x4(sb + SM_BHI + base, bh[jp]);
                ldmat_x4(sb + SM_BLO + base, bl[jp]);
            }
#pragma unroll
            for (int ms = 0; ms < 2; ms++)
#pragma unroll
                for (int jp = 0; jp < 4; jp++) {
                    mma_bf16(acc[ms][2*jp],   ah[ms], &bh[jp][0]);
                    mma_bf16(acc[ms][2*jp+1], ah[ms], &bh[jp][2]);
                    mma_bf16(acc[ms][2*jp],   ah[ms], &bl[jp][0]);
                    mma_bf16(acc[ms][2*jp+1], ah[ms], &bl[jp][2]);
                    mma_bf16(acc[ms][2*jp],   al[ms], &bh[jp][0]);
                    mma_bf16(acc[ms][2*jp+1], al[ms], &bh[jp][2]);
                }
        }
    }
    // epilogue: y[n][r*128 + col]
    const int g = lane >> 2, tig = lane & 3;
#pragma unroll
    for (int ms = 0; ms < 2; ms++) {
        const int r1 = row0 + wm0 + ms * 16 + g;
        const int r2 = r1 + 8;
#pragma unroll
        for (int nt = 0; nt < 8; nt++) {
            const int col = r * CDIM + wn0 + nt * 8 + tig * 2;
            if (r1 < Nn)
                *reinterpret_cast<float2*>(y + (size_t)r1 * NREL + col) =
                    make_float2(acc[ms][nt][0], acc[ms][nt][1]);
            if (r2 < Nn)
                *reinterpret_cast<float2*>(y + (size_t)r2 * NREL + col) =
                    make_float2(acc[ms][nt][2], acc[ms][nt][3]);
        }
    }
}

// ---------------- phase 4: root GEMM (masked K=512) + bias -> out ----------
__global__ __launch_bounds__(256) void k_root(const float* __restrict__ x,
                                              const int* __restrict__ tnt,
                                              const float* __restrict__ root_b,
                                              float* __restrict__ out, int Nn) {
    extern __shared__ char smem[];
    const uint32_t sb = smem_u32(smem);
    const int tid = threadIdx.x, wid = tid >> 5, lane = tid & 31;
    const int row0 = blockIdx.x * 128;

    const int m = tid >> 1;
    const int khalf = (tid & 1) * 32;
    const int n = row0 + m;
    const bool nval = (n < Nn);
    const int mytype = nval ? tnt[n] : -1;

    const int wm0 = (wid & 3) * 32;
    const int wn0 = (wid >> 2) * 64;
    const int quad = lane >> 3, lrow = lane & 7;
    const int a_roff = ((quad & 1) * 8 + lrow) * SROW + ((quad >> 1) * 8) * 2;
    const int b_roff = ((quad >> 1) * 8 + lrow) * SROW + ((quad & 1) * 8) * 2;

    float acc[2][8][4];
#pragma unroll
    for (int i = 0; i < 2; i++)
#pragma unroll
        for (int j = 0; j < 8; j++)
#pragma unroll
            for (int q = 0; q < 4; q++) acc[i][j][q] = 0.f;

    for (int c = 0; c < 8; ++c) {
        if (c) __syncthreads();
        const int t = c >> 1;
        const int coloff = (c & 1) * 64 + khalf;
        float4 v[8];
        if (nval && mytype == t) {
            const float4* src = reinterpret_cast<const float4*>(x + (size_t)n * CDIM + coloff);
#pragma unroll
            for (int i = 0; i < 8; i++) v[i] = src[i];
        } else {
#pragma unroll
            for (int i = 0; i < 8; i++) v[i] = make_float4(0.f, 0.f, 0.f, 0.f);
        }
        store_hilo(sb + SM_AHI + m * SROW, sb + SM_ALO + m * SROW, khalf, v);
        {
            const char* srcH = g_RBh + (size_t)c * BTILE_BYTES;
            const char* srcL = g_RBl + (size_t)c * BTILE_BYTES;
#pragma unroll
            for (int i = 0; i < 4; i++) {
                int u = tid + i * 256;
                int row = u >> 3, seg = (u & 7) * 16;
                *reinterpret_cast<float4*>(smem + SM_BHI + row * SROW + seg) =
                    *reinterpret_cast<const float4*>(srcH + row * BROW_BYTES + seg);
                *reinterpret_cast<float4*>(smem + SM_BLO + row * SROW + seg) =
                    *reinterpret_cast<const float4*>(srcL + row * BROW_BYTES + seg);
            }
        }
        __syncthreads();
#pragma unroll
        for (int s = 0; s < 4; s++) {
            uint32_t ah[2][4], al[2][4], bh[4][4], bl[4][4];
#pragma unroll
            for (int ms = 0; ms < 2; ms++) {
                uint32_t base = (wm0 + ms * 16) * SROW + (s * 16) * 2 + a_roff;
                ldmat_x4(sb + SM_AHI + base, ah[ms]);
                ldmat_x4(sb + SM_ALO + base, al[ms]);
            }
#pragma unroll
            for (int jp = 0; jp < 4; jp++) {
                uint32_t base = (wn0 + jp * 16) * SROW + (s * 16) * 2 + b_roff;
                ldmat_x4(sb + SM_BHI + base, bh[jp]);
                ldmat_x4(sb + SM_BLO + base, bl[jp]);
            }
#pragma unroll
            for (int ms = 0; ms < 2; ms++)
#pragma unroll
                for (int jp = 0; jp < 4; jp++) {
                    mma_bf16(acc[ms][2*jp],   ah[ms], &bh[jp][0]);
                    mma_bf16(acc[ms][2*jp+1], ah[ms], &bh[jp][2]);
                    mma_bf16(acc[ms][2*jp],   ah[ms], &bl[jp][0]);
                    mma_bf16(acc[ms][2*jp+1], ah[ms], &bl[jp][2]);
                    mma_bf16(acc[ms][2*jp],   al[ms], &bh[jp][0]);
                    mma_bf16(acc[ms][2*jp+1], al[ms], &bh[jp][2]);
                }
        }
    }
    const int g = lane >> 2, tig = lane & 3;
#pragma unroll
    for (int ms = 0; ms < 2; ms++) {
        const int r1 = row0 + wm0 + ms * 16 + g;
        const int r2 = r1 + 8;
        const int t1 = (r1 < Nn) ? tnt[r1] : 0;
        const int t2 = (r2 < Nn) ? tnt[r2] : 0;
#pragma unroll
        for (int nt = 0; nt < 8; nt++) {
            const int col = wn0 + nt * 8 + tig * 2;
            if (r1 < Nn) {
                float2 b1 = *reinterpret_cast<const float2*>(root_b + t1 * CDIM + col);
                *reinterpret_cast<float2*>(out + (size_t)r1 * CDIM + col) =
                    make_float2(acc[ms][nt][0] + b1.x, acc[ms][nt][1] + b1.y);
            }
            if (r2 < Nn) {
                float2 b2 = *reinterpret_cast<const float2*>(root_b + t2 * CDIM + col);
                *reinterpret_cast<float2*>(out + (size_t)r2 * CDIM + col) =
                    make_float2(acc[ms][nt][2] + b2.x, acc[ms][nt][3] + b2.y);
            }
        }
    }
}

// ---------------- phase 5: edge scatter of transformed feats ---------------
// one warp per edge: out[dst] += inv[dst,r] * y[src, r*128:(r+1)*128]
__global__ void k_edge(const float* __restrict__ y,
                       const int* __restrict__ ei,
                       const int* __restrict__ et,
                       float* __restrict__ out, int E) {
    int gtid = blockIdx.x * blockDim.x + threadIdx.x;
    int e = gtid >> 5;
    int lane = gtid & 31;
    if (e >= E) return;
    int src = ei[e];
    int dst = ei[E + e];
    int r = et[e];
    float s = g_inv[dst * RNUM + r];
    float4 v = reinterpret_cast<const float4*>(y + (size_t)src * NREL + r * CDIM)[lane];
    v.x *= s; v.y *= s; v.z *= s; v.w *= s;
    float* base = out + (size_t)dst * CDIM + lane * 4;
    asm volatile("red.global.add.v4.f32 [%0], {%1,%2,%3,%4};"
                 :: "l"(base), "f"(v.x), "f"(v.y), "f"(v.z), "f"(v.w) : "memory");
}

// ---------------------------------------------------------------------------
extern "C" void kernel_launch(void* const* d_in, const int* in_sizes, int n_in,
                              void* d_out, int out_size) {
    const float* x      = (const float*)d_in[0];
    const int*   ei     = (const int*)d_in[1];
    const int*   et     = (const int*)d_in[2];
    const int*   tnt    = (const int*)d_in[3];
    const float* rel_w  = (const float*)d_in[4];
    const float* root_w = (const float*)d_in[5];
    const float* root_b = (const float*)d_in[6];
    float* out = (float*)d_out;

    int E  = in_sizes[2];
    int Nn = in_sizes[3];
    int nseg = Nn * RNUM;
    int mt = (Nn + 127) / 128;

    cudaFuncSetAttribute(k_transform, cudaFuncAttributeMaxDynamicSharedMemorySize, SM_TOTAL);
    cudaFuncSetAttribute(k_root, cudaFuncAttributeMaxDynamicSharedMemorySize, SM_TOTAL);

    float* y;
    cudaGetSymbolAddress((void**)&y, g_y);

    k_zero<<<(nseg + 255) / 256, 256>>>(nseg);
    k_buildB<<<((NREL + KROOT) * CDIM + 255) / 256, 256>>>(rel_w, root_w);
    k_count<<<(E + 255) / 256, 256>>>(ei, et, E);
    k_inv<<<(nseg + 255) / 256, 256>>>(nseg);
    k_transform<<<dim3(RNUM, mt), 256, SM_TOTAL>>>(x, y, Nn);
    k_root<<<mt, 256, SM_TOTAL>>>(x, tnt, root_b, out, Nn);
    k_edge<<<((size_t)E * 32 + 255) / 256, 256>>>(y, ei, et, out, E);
}

// round 5
// speedup vs baseline: 1.8459x; 1.1511x over previous
#include <cuda_runtime.h>
#include <cuda_bf16.h>
#include <cstdint>

#define CDIM 128
#define RNUM 7
#define TNUM 4
#define MAXN 100000
#define MAXE 2000000
#define NCHK 22                      /* 14 rel chunks + 8 root chunks (K=64 each) */
#define SROW 144                     /* padded smem row stride bytes (64 bf16 + pad) */
#define ATB  (128 * SROW)            /* one A tile buffer: 18432 B */
#define SM_TOTAL (4 * ATB)           /* chunk0 hi, chunk0 lo, chunk1 hi, chunk1 lo */

// ---------------- device scratch ----------------
__device__ int g_cnt[MAXN * RNUM];
__device__ int g_off[MAXN * RNUM];
__device__ int g_cur[MAXN * RNUM];
__device__ int g_bsum[1024];
__device__ int g_esrc[MAXE];
// B fragments: [chunk][j(8)][s(4)][h(2)][lane(32)] as uint4 (4 regs per lane)
__device__ __align__(16) uint4 g_Bf[NCHK * 8 * 4 * 2 * 32];

// ---------------- helpers ----------------
__device__ __forceinline__ uint32_t smem_u32(const void* p) {
    uint32_t a;
    asm("{ .reg .u64 t; cvta.to.shared.u64 t, %1; cvt.u32.u64 %0, t; }" : "=r"(a) : "l"(p));
    return a;
}
__device__ __forceinline__ void ldmat_x4(uint32_t addr, uint32_t* r) {
    asm volatile("ldmatrix.sync.aligned.m8n8.x4.shared.b16 {%0,%1,%2,%3}, [%4];"
                 : "=r"(r[0]), "=r"(r[1]), "=r"(r[2]), "=r"(r[3]) : "r"(addr));
}
__device__ __forceinline__ void mma4(float* d, const uint32_t* a, uint32_t b0, uint32_t b1) {
    asm volatile("mma.sync.aligned.m16n8k16.row.col.f32.bf16.bf16.f32 "
                 "{%0,%1,%2,%3}, {%4,%5,%6,%7}, {%8,%9}, {%0,%1,%2,%3};"
                 : "+f"(d[0]), "+f"(d[1]), "+f"(d[2]), "+f"(d[3])
                 : "r"(a[0]), "r"(a[1]), "r"(a[2]), "r"(a[3]), "r"(b0), "r"(b1));
}
__device__ __forceinline__ uint32_t packbf(float a, float b) {
    __nv_bfloat16 h0 = __float2bfloat16(a), h1 = __float2bfloat16(b);
    return (uint32_t)__bfloat16_as_ushort(h0) | ((uint32_t)__bfloat16_as_ushort(h1) << 16);
}

// ---------------- phase 0: zero counts ----------------
__global__ void k_zero(int nseg) {
    int i = blockIdx.x * blockDim.x + threadIdx.x;
    if (i < nseg) g_cnt[i] = 0;
}
// ---------------- phase 1: histogram ----------------
__global__ void k_count(const int* __restrict__ ei, const int* __restrict__ et, int E) {
    int e = blockIdx.x * blockDim.x + threadIdx.x;
    if (e >= E) return;
    atomicAdd(&g_cnt[ei[E + e] * RNUM + et[e]], 1);
}
// ---------------- phase 2: exclusive scan (3 kernels) ----------------
__global__ void k_scan1(int nseg) {
    __shared__ int wsum[8];
    int tid = threadIdx.x;
    int base = blockIdx.x * 1024 + tid * 4;
    int v0 = 0, v1 = 0, v2 = 0, v3 = 0;
    if (base + 0 < nseg) v0 = g_cnt[base + 0];
    if (base + 1 < nseg) v1 = g_cnt[base + 1];
    if (base + 2 < nseg) v2 = g_cnt[base + 2];
    if (base + 3 < nseg) v3 = g_cnt[base + 3];
    int tot = v0 + v1 + v2 + v3;
    int lane = tid & 31, wid = tid >> 5;
    int inc = tot;
#pragma unroll
    for (int d = 1; d < 32; d <<= 1) {
        int t = __shfl_up_sync(0xffffffff, inc, d);
        if (lane >= d) inc += t;
    }
    if (lane == 31) wsum[wid] = inc;
    __syncthreads();
    if (wid == 0) {
        int w = (lane < 8) ? wsum[lane] : 0;
#pragma unroll
        for (int d = 1; d < 8; d <<= 1) {
            int t = __shfl_up_sync(0xffffffff, w, d);
            if (lane >= d) w += t;
        }
        if (lane < 8) wsum[lane] = w;
    }
    __syncthreads();
    int excl = inc - tot + (wid ? wsum[wid - 1] : 0);
    if (base + 0 < nseg) g_off[base + 0] = excl;
    if (base + 1 < nseg) g_off[base + 1] = excl + v0;
    if (base + 2 < nseg) g_off[base + 2] = excl + v0 + v1;
    if (base + 3 < nseg) g_off[base + 3] = excl + v0 + v1 + v2;
    if (tid == 255) g_bsum[blockIdx.x] = wsum[7];
}
__global__ void k_scan2(int nb) {
    __shared__ int sm[1024];
    int tid = threadIdx.x;
    int v = (tid < nb) ? g_bsum[tid] : 0;
    sm[tid] = v;
    __syncthreads();
    for (int d = 1; d < 1024; d <<= 1) {
        int t = (tid >= d) ? sm[tid - d] : 0;
        __syncthreads();
        sm[tid] += t;
        __syncthreads();
    }
    if (tid < nb) g_bsum[tid] = sm[tid] - v;
}
__global__ void k_scan3(int nseg) {
    int i = blockIdx.x * blockDim.x + threadIdx.x;
    if (i < nseg) {
        int v = g_off[i] + g_bsum[i >> 10];
        g_off[i] = v;
        g_cur[i] = v;
    }
}
// ---------------- phase 3: scatter srcs into segment-sorted order ----------
__global__ void k_scatter(const int* __restrict__ ei, const int* __restrict__ et, int E) {
    int e = blockIdx.x * blockDim.x + threadIdx.x;
    if (e >= E) return;
    int s = ei[E + e] * RNUM + et[e];
    int p = atomicAdd(&g_cur[s], 1);
    g_esrc[p] = ei[e];
}
// ---------------- phase 4: build B fragments (hi/lo, exact mma layout) -----
__global__ void k_buildBf(const float* __restrict__ rel_w,
                          const float* __restrict__ root_w) {
    int idx = blockIdx.x * blockDim.x + threadIdx.x;  // over NCHK*8*4*32
    if (idx >= NCHK * 8 * 4 * 32) return;
    int lane = idx & 31;
    int s = (idx >> 5) & 3;
    int j = (idx >> 7) & 7;
    int chunk = idx >> 10;
    uint32_t hi[4], lo[4];
#pragma unroll
    for (int q = 0; q < 4; q++) {
        int n = j * 16 + ((q & 2) ? 8 : 0) + (lane >> 2);
        int kk = s * 16 + ((q & 1) ? 8 : 0) + 2 * (lane & 3);
        float w0, w1;
        if (chunk < 14) {
            int r = chunk >> 1, kb = (chunk & 1) * 64;
            const float* p = rel_w + ((size_t)(r * CDIM + n)) * CDIM + kb + kk;
            w0 = p[0]; w1 = p[1];
        } else {
            int rc = chunk - 14;
            int t = rc >> 1, kb = (rc & 1) * 64;
            const float* p = root_w + ((size_t)(t * CDIM + n)) * CDIM + kb + kk;
            w0 = p[0]; w1 = p[1];
        }
        __nv_bfloat16 h0 = __float2bfloat16(w0), h1 = __float2bfloat16(w1);
        float r0 = w0 - __bfloat162float(h0), r1 = w1 - __bfloat162float(h1);
        hi[q] = (uint32_t)__bfloat16_as_ushort(h0) | ((uint32_t)__bfloat16_as_ushort(h1) << 16);
        lo[q] = packbf(r0, r1);
    }
    size_t base = ((((size_t)chunk * 8 + j) * 4 + s) * 2) * 32 + lane;
    g_Bf[base]      = make_uint4(hi[0], hi[1], hi[2], hi[3]);
    g_Bf[base + 32] = make_uint4(lo[0], lo[1], lo[2], lo[3]);
}

// ---------------- phase 5: fully fused gather + GEMM + epilogue -------------
__device__ __forceinline__ void storeA(uint32_t sb, int m, int lane, float4 v) {
    int chunk = lane >> 4;
    uint32_t boff = (uint32_t)m * SROW + (lane & 15) * 8;
    uint32_t hp0 = packbf(v.x, v.y), hp1 = packbf(v.z, v.w);
    float rx = v.x - __bfloat162float(__float2bfloat16(v.x));
    float ry = v.y - __bfloat162float(__float2bfloat16(v.y));
    float rz = v.z - __bfloat162float(__float2bfloat16(v.z));
    float rw = v.w - __bfloat162float(__float2bfloat16(v.w));
    uint32_t lp0 = packbf(rx, ry), lp1 = packbf(rz, rw);
    asm volatile("st.shared.v2.b32 [%0], {%1,%2};"
                 :: "r"(sb + (chunk * 2 + 0) * ATB + boff), "r"(hp0), "r"(hp1) : "memory");
    asm volatile("st.shared.v2.b32 [%0], {%1,%2};"
                 :: "r"(sb + (chunk * 2 + 1) * ATB + boff), "r"(lp0), "r"(lp1) : "memory");
}

__global__ __launch_bounds__(512) void k_fused(const float* __restrict__ x,
                                               const int* __restrict__ tnt,
                                               const float* __restrict__ root_b,
                                               float* __restrict__ out, int Nn) {
    extern __shared__ char smem[];
    const uint32_t sb = smem_u32(smem);
    const int tid = threadIdx.x, wid = tid >> 5, lane = tid & 31;
    const int row0 = blockIdx.x * 128;
    const int wm0 = (wid & 7) * 16;       // 16-row GEMM m-tile per warp
    const int wn0 = (wid >> 3) * 64;      // 64-col n-tile per warp pair-group
    const int jbase = (wid >> 3) * 4;
    const int quad = lane >> 3, lrow = lane & 7;
    const int a_roff = ((quad & 1) * 8 + lrow) * SROW + ((quad >> 1) * 8) * 2;
    const float4* x4 = reinterpret_cast<const float4*>(x);

    float acc[8][4];
#pragma unroll
    for (int j = 0; j < 8; j++)
#pragma unroll
        for (int q = 0; q < 4; q++) acc[j][q] = 0.f;

    // ------- 7 relations + 4 masked root types = 11 A-phases, 22 GEMM chunks
    for (int phase = 0; phase < RNUM + TNUM; ++phase) {
        __syncthreads();   // prior GEMM done reading A
        // ---- build A (8 rows per warp) ----
#pragma unroll 1
        for (int i = 0; i < 8; i++) {
            int m = wid * 8 + i;
            int dst = row0 + m;
            float4 v = make_float4(0.f, 0.f, 0.f, 0.f);
            if (dst < Nn) {
                if (phase < RNUM) {
                    int s = dst * RNUM + phase;
                    int o0 = g_off[s], c = g_cnt[s];
                    float4 a0 = make_float4(0.f, 0.f, 0.f, 0.f);
                    float4 a1 = make_float4(0.f, 0.f, 0.f, 0.f);
                    int j = 0;
                    for (; j + 2 <= c; j += 2) {
                        int s0 = g_esrc[o0 + j], s1 = g_esrc[o0 + j + 1];
                        float4 u0 = x4[(size_t)s0 * 32 + lane];
                        float4 u1 = x4[(size_t)s1 * 32 + lane];
                        a0.x += u0.x; a0.y += u0.y; a0.z += u0.z; a0.w += u0.w;
                        a1.x += u1.x; a1.y += u1.y; a1.z += u1.z; a1.w += u1.w;
                    }
                    if (j < c) {
                        float4 u = x4[(size_t)g_esrc[o0 + j] * 32 + lane];
                        a0.x += u.x; a0.y += u.y; a0.z += u.z; a0.w += u.w;
                    }
                    float inv = 1.f / fmaxf((float)c, 1.f);
                    v.x = (a0.x + a1.x) * inv; v.y = (a0.y + a1.y) * inv;
                    v.z = (a0.z + a1.z) * inv; v.w = (a0.w + a1.w) * inv;
                } else {
                    int t = phase - RNUM;
                    if (tnt[dst] == t) v = x4[(size_t)dst * 32 + lane];
                }
            }
            storeA(sb, m, lane, v);
        }
        __syncthreads();
        // ---- GEMM: 2 K-chunks of 64 ----
        const int c0 = phase * 2;
#pragma unroll
        for (int cc = 0; cc < 2; cc++) {
            const int chunk = c0 + cc;
#pragma unroll
            for (int s = 0; s < 4; s++) {
                uint32_t ah[4], al[4];
                uint32_t abase = (uint32_t)wm0 * SROW + s * 32 + a_roff;
                ldmat_x4(sb + (cc * 2 + 0) * ATB + abase, ah);
                ldmat_x4(sb + (cc * 2 + 1) * ATB + abase, al);
#pragma unroll
                for (int jp = 0; jp < 4; jp++) {
                    const uint4* bp = g_Bf +
                        ((((size_t)chunk * 8 + (jbase + jp)) * 4 + s) * 2) * 32 + lane;
                    uint4 BH = bp[0];
                    uint4 BL = bp[32];
                    mma4(acc[2 * jp],     ah, BH.x, BH.y);
                    mma4(acc[2 * jp + 1], ah, BH.z, BH.w);
                    mma4(acc[2 * jp],     ah, BL.x, BL.y);
                    mma4(acc[2 * jp + 1], ah, BL.z, BL.w);
                    mma4(acc[2 * jp],     al, BH.x, BH.y);
                    mma4(acc[2 * jp + 1], al, BH.z, BH.w);
                }
            }
        }
    }

    // ---- epilogue: + root_b[tnt], single store ----
    const int g = lane >> 2, tig = lane & 3;
    const int r1 = row0 + wm0 + g;
    const int r2 = r1 + 8;
    const int t1 = (r1 < Nn) ? tnt[r1] : 0;
    const int t2 = (r2 < Nn) ? tnt[r2] : 0;
#pragma unroll
    for (int nt = 0; nt < 8; nt++) {
        const int col = wn0 + nt * 8 + tig * 2;
        if (r1 < Nn) {
            float2 b1 = *reinterpret_cast<const float2*>(root_b + t1 * CDIM + col);
            *reinterpret_cast<float2*>(out + (size_t)r1 * CDIM + col) =
                make_float2(acc[nt][0] + b1.x, acc[nt][1] + b1.y);
        }
        if (r2 < Nn) {
            float2 b2 = *reinterpret_cast<const float2*>(root_b + t2 * CDIM + col);
            *reinterpret_cast<float2*>(out + (size_t)r2 * CDIM + col) =
                make_float2(acc[nt][2] + b2.x, acc[nt][3] + b2.y);
        }
    }
}

// ---------------------------------------------------------------------------
extern "C" void kernel_launch(void* const* d_in, const int* in_sizes, int n_in,
                              void* d_out, int out_size) {
    const float* x      = (const float*)d_in[0];
    const int*   ei     = (const int*)d_in[1];
    const int*   et     = (const int*)d_in[2];
    const int*   tnt    = (const int*)d_in[3];
    const float* rel_w  = (const float*)d_in[4];
    const float* root_w = (const float*)d_in[5];
    const float* root_b = (const float*)d_in[6];
    float* out = (float*)d_out;

    int E  = in_sizes[2];
    int Nn = in_sizes[3];
    int nseg = Nn * RNUM;
    int nb = (nseg + 1023) / 1024;

    cudaFuncSetAttribute(k_fused, cudaFuncAttributeMaxDynamicSharedMemorySize, SM_TOTAL);

    k_zero<<<(nseg + 255) / 256, 256>>>(nseg);
    k_count<<<(E + 255) / 256, 256>>>(ei, et, E);
    k_scan1<<<nb, 256>>>(nseg);
    k_scan2<<<1, 1024>>>(nb);
    k_scan3<<<(nseg + 255) / 256, 256>>>(nseg);
    k_scatter<<<(E + 255) / 256, 256>>>(ei, et, E);
    k_buildBf<<<(NCHK * 8 * 4 * 32 + 255) / 256, 256>>>(rel_w, root_w);
    k_fused<<<(Nn + 127) / 128, 512, SM_TOTAL>>>(x, tnt, root_b, out, Nn);
}